// round 2
// baseline (speedup 1.0000x reference)
#include <cuda_runtime.h>
#include <cstdint>

#define NL 8
#define T_STATIC 524288u   // 2^19
#define T_XY     32768u    // 2^15
#define T_PL     8192u     // 2^13
#define P1 2654435761u
#define P2 805459861u
#define BS 128
#define W  (BS + 1)

#define NXY (NL * T_XY)    // 262144
#define NPL (NL * T_PL)    // 65536

__device__ float g_scales[NL];
__device__ float g_red_xy[NXY];
__device__ float g_red_xz[NPL];
__device__ float g_red_yz[NPL];

// ---------------------------------------------------------------------------
// One kernel: init scales (double, matches numpy) + fold time-blend and
// Lagrange basis into scalar tables for all three planes.
// ---------------------------------------------------------------------------
__global__ void reduce_all_kernel(const float4* __restrict__ txy,
                                  const float4* __restrict__ txz,
                                  const float4* __restrict__ tyz,
                                  const float* __restrict__ tptr) {
    int g = blockIdx.x * blockDim.x + threadIdx.x;
    if (g < NL) {
        double s = exp2((double)g * (6.0 / 7.0)) * 512.0 - 1.0;
        g_scales[g] = (float)s;
    }

    float t = __ldg(tptr);
    float idxf = t * 7.0f;               // t * (TIME_RES - 1)
    float fi1 = floorf(idxf);
    int i1 = (int)fi1;
    int i2 = (int)ceilf(idxf);
    float w2 = idxf - fi1;
    float w1 = 1.0f - w2;

    float tn[4] = {0.0f, 1.0f / 3.0f, 2.0f / 3.0f, 1.0f};
    float coef[4];
#pragma unroll
    for (int ii = 0; ii < 4; ii++) {
        float c = 1.0f;
#pragma unroll
        for (int m = 0; m < 4; m++)
            if (m != ii) c = c * (t - tn[m]) / (tn[ii] - tn[m]);
        coef[ii] = c;
    }

    const float4* tab;
    float* dst;
    int e, total;
    if (g < (int)NXY)                  { tab = txy; dst = g_red_xy; e = g;               total = NXY; }
    else if (g < (int)(NXY + NPL))     { tab = txz; dst = g_red_xz; e = g - NXY;         total = NPL; }
    else if (g < (int)(NXY + 2 * NPL)) { tab = tyz; dst = g_red_yz; e = g - NXY - NPL;   total = NPL; }
    else return;

    float4 v1 = __ldg(tab + (size_t)i1 * total + e);
    float4 v2 = __ldg(tab + (size_t)i2 * total + e);
    dst[e] = coef[0] * (w1 * v1.x + w2 * v2.x)
           + coef[1] * (w1 * v1.y + w2 * v2.y)
           + coef[2] * (w1 * v1.z + w2 * v2.z)
           + coef[3] * (w1 * v1.w + w2 * v2.w);
}

// ---------------------------------------------------------------------------
// Dynamic 2D plane lookup. First dim uses prime 1 => when ua is even the two
// a-corner entries are an aligned pair {e, e^1}: one float2 load covers both.
// ---------------------------------------------------------------------------
__device__ __forceinline__ void dyn_plane(float a, float b,
                                          const float* __restrict__ red,
                                          uint32_t mask,
                                          const float* sc,
                                          float* srow /* s + row0*W + tid */) {
#pragma unroll
    for (int l = 0; l < NL; l++) {
        float s = sc[l];
        float pa = __fadd_rn(__fmul_rn(a, s), 0.5f);
        float pb = __fadd_rn(__fmul_rn(b, s), 0.5f);
        float ba = floorf(pa), bb = floorf(pb);
        float fa = pa - ba, fb = pb - bb;
        uint32_t ua = (uint32_t)ba, ub = (uint32_t)bb;
        uint32_t hb0 = ub * P1, hb1 = hb0 + P1;
        uint32_t e00 = (ua ^ hb0) & mask;
        uint32_t e01 = (ua ^ hb1) & mask;
        const float* r = red + (size_t)l * (mask + 1u);

        float v00, v10, v01, v11;
        if ((ua & 1u) == 0u) {
            // e10 == e00^1, e11 == e01^1 (no carry out of bit 0)
            float2 q0 = __ldg((const float2*)(r + (e00 & ~1u)));
            float2 q1 = __ldg((const float2*)(r + (e01 & ~1u)));
            if (e00 & 1u) { v00 = q0.y; v10 = q0.x; } else { v00 = q0.x; v10 = q0.y; }
            if (e01 & 1u) { v01 = q1.y; v11 = q1.x; } else { v01 = q1.x; v11 = q1.y; }
        } else {
            uint32_t e10 = ((ua + 1u) ^ hb0) & mask;
            uint32_t e11 = ((ua + 1u) ^ hb1) & mask;
            v00 = __ldg(r + e00); v10 = __ldg(r + e10);
            v01 = __ldg(r + e01); v11 = __ldg(r + e11);
        }

        float ga = 1.0f - fa, gb = 1.0f - fb;
        float acc = (ga * gb) * v00;
        acc += (fa * gb) * v10;
        acc += (ga * fb) * v01;
        acc += (fa * fb) * v11;
        srow[l * W] = acc;
    }
}

// ---------------------------------------------------------------------------
// Main: compute per point into smem (transposed), then coalesced stores.
// ---------------------------------------------------------------------------
__global__ void __launch_bounds__(BS)
main_kernel(const float* __restrict__ x,
            const float4* __restrict__ tstat,
            float* __restrict__ out_s,
            float* __restrict__ out_d,
            int N) {
    __shared__ float s[56 * W];

    int base = blockIdx.x * BS;
    int tid = threadIdx.x;
    int i = base + tid;

    float sc[NL];
#pragma unroll
    for (int l = 0; l < NL; l++) sc[l] = g_scales[l];

    if (i < N) {
        float x0 = __ldg(x + 3 * (size_t)i + 0);
        float x1 = __ldg(x + 3 * (size_t)i + 1);
        float x2 = __ldg(x + 3 * (size_t)i + 2);

        // ---- static 3D grid ----
#pragma unroll
        for (int l = 0; l < NL; l++) {
            float scl = sc[l];
            float px = __fadd_rn(__fmul_rn(x0, scl), 0.5f);
            float py = __fadd_rn(__fmul_rn(x1, scl), 0.5f);
            float pz = __fadd_rn(__fmul_rn(x2, scl), 0.5f);
            float bx = floorf(px), by = floorf(py), bz = floorf(pz);
            float fx = px - bx, fy = py - by, fz = pz - bz;
            uint32_t ux = (uint32_t)bx, uy = (uint32_t)by, uz = (uint32_t)bz;
            uint32_t hx0 = ux,      hx1 = ux + 1u;
            uint32_t hy0 = uy * P1, hy1 = hy0 + P1;
            uint32_t hz0 = uz * P2, hz1 = hz0 + P2;
            float gx = 1.0f - fx, gy = 1.0f - fy, gz = 1.0f - fz;
            const float4* tl = tstat + (size_t)l * T_STATIC;

            float a0 = 0.f, a1 = 0.f, a2 = 0.f, a3 = 0.f;
#pragma unroll
            for (int c = 0; c < 8; c++) {
                uint32_t h = ((c & 1) ? hx1 : hx0)
                           ^ ((c & 2) ? hy1 : hy0)
                           ^ ((c & 4) ? hz1 : hz0);
                float w = (((c & 1) ? fx : gx) * ((c & 2) ? fy : gy))
                        * ((c & 4) ? fz : gz);
                float4 v = __ldg(tl + (h & (T_STATIC - 1u)));
                a0 += w * v.x; a1 += w * v.y; a2 += w * v.z; a3 += w * v.w;
            }
            s[(4 * l + 0) * W + tid] = a0;
            s[(4 * l + 1) * W + tid] = a1;
            s[(4 * l + 2) * W + tid] = a2;
            s[(4 * l + 3) * W + tid] = a3;
        }

        // ---- dynamic planes (reduced scalar tables) ----
        dyn_plane(x0, x1, g_red_xy, T_XY - 1u, sc, s + 32 * W + tid);
        dyn_plane(x0, x2, g_red_xz, T_PL - 1u, sc, s + 40 * W + tid);
        dyn_plane(x1, x2, g_red_yz, T_PL - 1u, sc, s + 48 * W + tid);
    }

    __syncthreads();

    int npts = N - base;
    if (npts > BS) npts = BS;

    // ---- coalesced stores: static region [base*32, +npts*32) ----
    {
        float4* o4 = (float4*)(out_s + (size_t)base * 32);
        int tot = npts * 8;
        for (int e = tid; e < tot; e += BS) {
            int k = e & 7;
            int p = e >> 3;
            int c = 4 * k;
            float4 v = make_float4(s[(c + 0) * W + p], s[(c + 1) * W + p],
                                   s[(c + 2) * W + p], s[(c + 3) * W + p]);
            o4[e] = v;
        }
    }
    // ---- dynamic region [base*24, +npts*24) ----
    {
        float4* o4 = (float4*)(out_d + (size_t)base * 24);
        int tot = npts * 6;
        for (int e = tid; e < tot; e += BS) {
            int k = e % 6;
            int p = e / 6;
            int c = 32 + 4 * k;
            float4 v = make_float4(s[(c + 0) * W + p], s[(c + 1) * W + p],
                                   s[(c + 2) * W + p], s[(c + 3) * W + p]);
            o4[e] = v;
        }
    }
}

// ---------------------------------------------------------------------------
extern "C" void kernel_launch(void* const* d_in, const int* in_sizes, int n_in,
                              void* d_out, int out_size) {
    const float* x     = (const float*)d_in[0];
    const float* tptr  = (const float*)d_in[1];
    const float* tstat = (const float*)d_in[2];
    const float* txy   = (const float*)d_in[3];
    const float* txz   = (const float*)d_in[4];
    const float* tyz   = (const float*)d_in[5];

    int N = in_sizes[0] / 3;
    float* out_s = (float*)d_out;
    float* out_d = (float*)d_out + (size_t)N * 32;

    int total_red = NXY + 2 * NPL;
    reduce_all_kernel<<<(total_red + 255) / 256, 256>>>(
        (const float4*)txy, (const float4*)txz, (const float4*)tyz, tptr);

    main_kernel<<<(N + BS - 1) / BS, BS>>>(x, (const float4*)tstat, out_s, out_d, N);
}

// round 3
// speedup vs baseline: 1.2923x; 1.2923x over previous
#include <cuda_runtime.h>
#include <cstdint>

#define NL 8
#define T_STATIC 524288u   // 2^19
#define T_XY     32768u    // 2^15
#define T_PL     8192u     // 2^13
#define P1 2654435761u
#define P2 805459861u

#define NXY (NL * T_XY)    // 262144
#define NPL (NL * T_PL)    // 65536

__device__ float g_scales[NL];
__device__ float g_red_xy[NXY];
__device__ float g_red_xz[NPL];
__device__ float g_red_yz[NPL];

// ---------------------------------------------------------------------------
// Init scales (double, matches numpy) + fold time-blend and Lagrange basis
// into scalar tables for all three planes.
// ---------------------------------------------------------------------------
__global__ void reduce_all_kernel(const float4* __restrict__ txy,
                                  const float4* __restrict__ txz,
                                  const float4* __restrict__ tyz,
                                  const float* __restrict__ tptr) {
    int g = blockIdx.x * blockDim.x + threadIdx.x;
    if (g < NL) {
        double s = exp2((double)g * (6.0 / 7.0)) * 512.0 - 1.0;
        g_scales[g] = (float)s;
    }

    float t = __ldg(tptr);
    float idxf = t * 7.0f;               // t * (TIME_RES - 1)
    float fi1 = floorf(idxf);
    int i1 = (int)fi1;
    int i2 = (int)ceilf(idxf);
    float w2 = idxf - fi1;
    float w1 = 1.0f - w2;

    float tn[4] = {0.0f, 1.0f / 3.0f, 2.0f / 3.0f, 1.0f};
    float coef[4];
#pragma unroll
    for (int ii = 0; ii < 4; ii++) {
        float c = 1.0f;
#pragma unroll
        for (int m = 0; m < 4; m++)
            if (m != ii) c = c * (t - tn[m]) / (tn[ii] - tn[m]);
        coef[ii] = c;
    }

    const float4* tab;
    float* dst;
    int e, total;
    if (g < (int)NXY)                  { tab = txy; dst = g_red_xy; e = g;             total = NXY; }
    else if (g < (int)(NXY + NPL))     { tab = txz; dst = g_red_xz; e = g - NXY;       total = NPL; }
    else if (g < (int)(NXY + 2 * NPL)) { tab = tyz; dst = g_red_yz; e = g - NXY - NPL; total = NPL; }
    else return;

    float4 v1 = __ldg(tab + (size_t)i1 * total + e);
    float4 v2 = __ldg(tab + (size_t)i2 * total + e);
    dst[e] = coef[0] * (w1 * v1.x + w2 * v2.x)
           + coef[1] * (w1 * v1.y + w2 * v2.y)
           + coef[2] * (w1 * v1.z + w2 * v2.z)
           + coef[3] * (w1 * v1.w + w2 * v2.w);
}

// ---------------------------------------------------------------------------
// Static 3D hash-grid: one thread per point, 8 levels x 8 corner gathers.
// Partial unroll keeps register pressure low while giving MLP=16.
// ---------------------------------------------------------------------------
__global__ void __launch_bounds__(256)
static_kernel(const float* __restrict__ x,
              const float4* __restrict__ tstat,
              float* __restrict__ out_s,
              int N) {
    int i = blockIdx.x * blockDim.x + threadIdx.x;
    if (i >= N) return;

    float x0 = __ldg(x + 3 * (size_t)i + 0);
    float x1 = __ldg(x + 3 * (size_t)i + 1);
    float x2 = __ldg(x + 3 * (size_t)i + 2);
    float* os = out_s + (size_t)i * 32;

#pragma unroll 2
    for (int l = 0; l < NL; l++) {
        float scl = g_scales[l];
        float px = __fadd_rn(__fmul_rn(x0, scl), 0.5f);
        float py = __fadd_rn(__fmul_rn(x1, scl), 0.5f);
        float pz = __fadd_rn(__fmul_rn(x2, scl), 0.5f);
        float bx = floorf(px), by = floorf(py), bz = floorf(pz);
        float fx = px - bx, fy = py - by, fz = pz - bz;
        uint32_t ux = (uint32_t)bx, uy = (uint32_t)by, uz = (uint32_t)bz;
        uint32_t hx0 = ux,      hx1 = ux + 1u;
        uint32_t hy0 = uy * P1, hy1 = hy0 + P1;
        uint32_t hz0 = uz * P2, hz1 = hz0 + P2;
        float gx = 1.0f - fx, gy = 1.0f - fy, gz = 1.0f - fz;
        const float4* tl = tstat + (size_t)l * T_STATIC;

        float a0 = 0.f, a1 = 0.f, a2 = 0.f, a3 = 0.f;
#pragma unroll
        for (int c = 0; c < 8; c++) {
            uint32_t h = ((c & 1) ? hx1 : hx0)
                       ^ ((c & 2) ? hy1 : hy0)
                       ^ ((c & 4) ? hz1 : hz0);
            float w = (((c & 1) ? fx : gx) * ((c & 2) ? fy : gy))
                    * ((c & 4) ? fz : gz);
            float4 v = __ldg(tl + (h & (T_STATIC - 1u)));
            a0 += w * v.x; a1 += w * v.y; a2 += w * v.z; a3 += w * v.w;
        }
        *(float4*)(os + l * 4) = make_float4(a0, a1, a2, a3);
    }
}

// ---------------------------------------------------------------------------
// Dynamic planes: one thread per point, 3 planes x 8 levels x 4 scalar
// gathers against the reduced tables.
// ---------------------------------------------------------------------------
__device__ __forceinline__ void dyn_plane(float a, float b,
                                          const float* __restrict__ red,
                                          uint32_t mask,
                                          float* __restrict__ od) {
    float d8[NL];
#pragma unroll 2
    for (int l = 0; l < NL; l++) {
        float s = g_scales[l];
        float pa = __fadd_rn(__fmul_rn(a, s), 0.5f);
        float pb = __fadd_rn(__fmul_rn(b, s), 0.5f);
        float ba = floorf(pa), bb = floorf(pb);
        float fa = pa - ba, fb = pb - bb;
        uint32_t ua = (uint32_t)ba, ub = (uint32_t)bb;
        uint32_t ha0 = ua,      ha1 = ua + 1u;
        uint32_t hb0 = ub * P1, hb1 = hb0 + P1;
        float ga = 1.0f - fa, gb = 1.0f - fb;
        const float* r = red + (size_t)l * (mask + 1u);

        float acc;
        acc  = (ga * gb) * __ldg(r + ((ha0 ^ hb0) & mask));
        acc += (fa * gb) * __ldg(r + ((ha1 ^ hb0) & mask));
        acc += (ga * fb) * __ldg(r + ((ha0 ^ hb1) & mask));
        acc += (fa * fb) * __ldg(r + ((ha1 ^ hb1) & mask));
        d8[l] = acc;
    }
    *(float4*)(od + 0) = make_float4(d8[0], d8[1], d8[2], d8[3]);
    *(float4*)(od + 4) = make_float4(d8[4], d8[5], d8[6], d8[7]);
}

__global__ void __launch_bounds__(256)
dyn_kernel(const float* __restrict__ x,
           float* __restrict__ out_d,
           int N) {
    int i = blockIdx.x * blockDim.x + threadIdx.x;
    if (i >= N) return;

    float x0 = __ldg(x + 3 * (size_t)i + 0);
    float x1 = __ldg(x + 3 * (size_t)i + 1);
    float x2 = __ldg(x + 3 * (size_t)i + 2);
    float* od = out_d + (size_t)i * 24;

    dyn_plane(x0, x1, g_red_xy, T_XY - 1u, od + 0);
    dyn_plane(x0, x2, g_red_xz, T_PL - 1u, od + 8);
    dyn_plane(x1, x2, g_red_yz, T_PL - 1u, od + 16);
}

// ---------------------------------------------------------------------------
extern "C" void kernel_launch(void* const* d_in, const int* in_sizes, int n_in,
                              void* d_out, int out_size) {
    const float* x     = (const float*)d_in[0];
    const float* tptr  = (const float*)d_in[1];
    const float* tstat = (const float*)d_in[2];
    const float* txy   = (const float*)d_in[3];
    const float* txz   = (const float*)d_in[4];
    const float* tyz   = (const float*)d_in[5];

    int N = in_sizes[0] / 3;
    float* out_s = (float*)d_out;
    float* out_d = (float*)d_out + (size_t)N * 32;

    int total_red = NXY + 2 * NPL;
    reduce_all_kernel<<<(total_red + 255) / 256, 256>>>(
        (const float4*)txy, (const float4*)txz, (const float4*)tyz, tptr);

    static_kernel<<<(N + 255) / 256, 256>>>(x, (const float4*)tstat, out_s, N);
    dyn_kernel<<<(N + 255) / 256, 256>>>(x, out_d, N);
}

// round 4
// speedup vs baseline: 1.4274x; 1.1046x over previous
#include <cuda_runtime.h>
#include <cstdint>

#define NL 8
#define T_STATIC 524288u   // 2^19
#define T_XY     32768u    // 2^15
#define T_PL     8192u     // 2^13
#define P1 2654435761u
#define P2 805459861u

#define NXY (NL * T_XY)    // 262144
#define NPL (NL * T_PL)    // 65536

__device__ float g_scales[NL];
__device__ float g_red_xy[NXY];
__device__ float g_red_xz[NPL];
__device__ float g_red_yz[NPL];

// ---------------------------------------------------------------------------
// Init scales (double, matches numpy) + fold time-blend and Lagrange basis
// into scalar tables for all three planes.
// ---------------------------------------------------------------------------
__global__ void reduce_all_kernel(const float4* __restrict__ txy,
                                  const float4* __restrict__ txz,
                                  const float4* __restrict__ tyz,
                                  const float* __restrict__ tptr) {
    int g = blockIdx.x * blockDim.x + threadIdx.x;
    if (g < NL) {
        double s = exp2((double)g * (6.0 / 7.0)) * 512.0 - 1.0;
        g_scales[g] = (float)s;
    }

    float t = __ldg(tptr);
    float idxf = t * 7.0f;               // t * (TIME_RES - 1)
    float fi1 = floorf(idxf);
    int i1 = (int)fi1;
    int i2 = (int)ceilf(idxf);
    float w2 = idxf - fi1;
    float w1 = 1.0f - w2;

    float tn[4] = {0.0f, 1.0f / 3.0f, 2.0f / 3.0f, 1.0f};
    float coef[4];
#pragma unroll
    for (int ii = 0; ii < 4; ii++) {
        float c = 1.0f;
#pragma unroll
        for (int m = 0; m < 4; m++)
            if (m != ii) c = c * (t - tn[m]) / (tn[ii] - tn[m]);
        coef[ii] = c;
    }

    const float4* tab;
    float* dst;
    int e, total;
    if (g < (int)NXY)                  { tab = txy; dst = g_red_xy; e = g;             total = NXY; }
    else if (g < (int)(NXY + NPL))     { tab = txz; dst = g_red_xz; e = g - NXY;       total = NPL; }
    else if (g < (int)(NXY + 2 * NPL)) { tab = tyz; dst = g_red_yz; e = g - NXY - NPL; total = NPL; }
    else return;

    float4 v1 = __ldg(tab + (size_t)i1 * total + e);
    float4 v2 = __ldg(tab + (size_t)i2 * total + e);
    dst[e] = coef[0] * (w1 * v1.x + w2 * v2.x)
           + coef[1] * (w1 * v1.y + w2 * v2.y)
           + coef[2] * (w1 * v1.z + w2 * v2.z)
           + coef[3] * (w1 * v1.w + w2 * v2.w);
}

// ---------------------------------------------------------------------------
// Static 3D hash-grid: one thread per (point, level). 8 independent gathers
// per thread, fully coalesced float4 stores (level is the fast thread index).
// ---------------------------------------------------------------------------
__global__ void __launch_bounds__(256)
static_kernel(const float* __restrict__ x,
              const float4* __restrict__ tstat,
              float4* __restrict__ out_s,   // [N*8] float4, level-major per point
              int total /* N*8 */) {
    int g = blockIdx.x * blockDim.x + threadIdx.x;
    if (g >= total) return;
    int p = g >> 3;
    int l = g & 7;

    float x0 = __ldg(x + 3 * (size_t)p + 0);
    float x1 = __ldg(x + 3 * (size_t)p + 1);
    float x2 = __ldg(x + 3 * (size_t)p + 2);

    float scl = g_scales[l];
    float px = __fadd_rn(__fmul_rn(x0, scl), 0.5f);
    float py = __fadd_rn(__fmul_rn(x1, scl), 0.5f);
    float pz = __fadd_rn(__fmul_rn(x2, scl), 0.5f);
    float bx = floorf(px), by = floorf(py), bz = floorf(pz);
    float fx = px - bx, fy = py - by, fz = pz - bz;
    uint32_t ux = (uint32_t)bx, uy = (uint32_t)by, uz = (uint32_t)bz;
    uint32_t hx0 = ux,      hx1 = ux + 1u;
    uint32_t hy0 = uy * P1, hy1 = hy0 + P1;
    uint32_t hz0 = uz * P2, hz1 = hz0 + P2;
    float gx = 1.0f - fx, gy = 1.0f - fy, gz = 1.0f - fz;
    const float4* tl = tstat + (size_t)l * T_STATIC;

    // issue all 8 gathers before consuming (max MLP)
    float4 v[8];
#pragma unroll
    for (int c = 0; c < 8; c++) {
        uint32_t h = ((c & 1) ? hx1 : hx0)
                   ^ ((c & 2) ? hy1 : hy0)
                   ^ ((c & 4) ? hz1 : hz0);
        v[c] = __ldg(tl + (h & (T_STATIC - 1u)));
    }

    float a0 = 0.f, a1 = 0.f, a2 = 0.f, a3 = 0.f;
#pragma unroll
    for (int c = 0; c < 8; c++) {
        float w = (((c & 1) ? fx : gx) * ((c & 2) ? fy : gy))
                * ((c & 4) ? fz : gz);
        a0 += w * v[c].x; a1 += w * v[c].y; a2 += w * v[c].z; a3 += w * v[c].w;
    }
    out_s[g] = make_float4(a0, a1, a2, a3);
}

// ---------------------------------------------------------------------------
// Dynamic planes: one thread per (point, plane). 8 levels x ~3 loads each
// (even-ua corners pair into one float2). Stores fully coalesced: thread
// (p, plane) writes 32B at out_d + p*96 + plane*32.
// ---------------------------------------------------------------------------
__global__ void __launch_bounds__(256)
dyn_kernel(const float* __restrict__ x,
           float4* __restrict__ out_d,   // [N*6] float4
           int total /* N*3 */) {
    int g = blockIdx.x * blockDim.x + threadIdx.x;
    if (g >= total) return;
    unsigned p = (unsigned)g / 3u;
    unsigned plane = (unsigned)g - 3u * p;

    float x0 = __ldg(x + 3 * (size_t)p + 0);
    float x1 = __ldg(x + 3 * (size_t)p + 1);
    float x2 = __ldg(x + 3 * (size_t)p + 2);

    float a = (plane == 2u) ? x1 : x0;
    float b = (plane == 0u) ? x1 : x2;
    const float* red = (plane == 0u) ? g_red_xy
                     : (plane == 1u) ? g_red_xz : g_red_yz;
    uint32_t mask = (plane == 0u) ? (T_XY - 1u) : (T_PL - 1u);
    uint32_t tsize = mask + 1u;

    float d8[NL];
#pragma unroll
    for (int l = 0; l < NL; l++) {
        float s = g_scales[l];
        float pa = __fadd_rn(__fmul_rn(a, s), 0.5f);
        float pb = __fadd_rn(__fmul_rn(b, s), 0.5f);
        float ba = floorf(pa), bb = floorf(pb);
        float fa = pa - ba, fb = pb - bb;
        uint32_t ua = (uint32_t)ba, ub = (uint32_t)bb;
        uint32_t hb0 = ub * P1, hb1 = hb0 + P1;
        uint32_t e00 = (ua ^ hb0) & mask;
        uint32_t e01 = (ua ^ hb1) & mask;
        const float* r = red + (size_t)l * tsize;

        float v00, v10, v01, v11;
        if ((ua & 1u) == 0u) {
            // e10 == e00^1, e11 == e01^1 (no carry out of bit 0)
            float2 q0 = __ldg((const float2*)(r + (e00 & ~1u)));
            float2 q1 = __ldg((const float2*)(r + (e01 & ~1u)));
            if (e00 & 1u) { v00 = q0.y; v10 = q0.x; } else { v00 = q0.x; v10 = q0.y; }
            if (e01 & 1u) { v01 = q1.y; v11 = q1.x; } else { v01 = q1.x; v11 = q1.y; }
        } else {
            uint32_t e10 = ((ua + 1u) ^ hb0) & mask;
            uint32_t e11 = ((ua + 1u) ^ hb1) & mask;
            v00 = __ldg(r + e00); v10 = __ldg(r + e10);
            v01 = __ldg(r + e01); v11 = __ldg(r + e11);
        }

        float ga = 1.0f - fa, gb = 1.0f - fb;
        float acc = (ga * gb) * v00;
        acc += (fa * gb) * v10;
        acc += (ga * fb) * v01;
        acc += (fa * fb) * v11;
        d8[l] = acc;
    }

    float4* od = out_d + (size_t)g * 2;
    od[0] = make_float4(d8[0], d8[1], d8[2], d8[3]);
    od[1] = make_float4(d8[4], d8[5], d8[6], d8[7]);
}

// ---------------------------------------------------------------------------
extern "C" void kernel_launch(void* const* d_in, const int* in_sizes, int n_in,
                              void* d_out, int out_size) {
    const float* x     = (const float*)d_in[0];
    const float* tptr  = (const float*)d_in[1];
    const float* tstat = (const float*)d_in[2];
    const float* txy   = (const float*)d_in[3];
    const float* txz   = (const float*)d_in[4];
    const float* tyz   = (const float*)d_in[5];

    int N = in_sizes[0] / 3;
    float* out_s = (float*)d_out;
    float* out_d = (float*)d_out + (size_t)N * 32;

    int total_red = NXY + 2 * NPL;
    reduce_all_kernel<<<(total_red + 255) / 256, 256>>>(
        (const float4*)txy, (const float4*)txz, (const float4*)tyz, tptr);

    int tot_s = N * 8;
    static_kernel<<<(tot_s + 255) / 256, 256>>>(x, (const float4*)tstat,
                                                (float4*)out_s, tot_s);

    int tot_d = N * 3;
    dyn_kernel<<<(tot_d + 255) / 256, 256>>>(x, (float4*)out_d, tot_d);
}

// round 5
// speedup vs baseline: 1.4308x; 1.0024x over previous
#include <cuda_runtime.h>
#include <cstdint>

#define NL 8
#define T_STATIC 524288u   // 2^19
#define T_XY     32768u    // 2^15
#define T_PL     8192u     // 2^13
#define P1 2654435761u
#define P2 805459861u

#define NXY (NL * T_XY)    // 262144
#define NPL (NL * T_PL)    // 65536

__device__ float g_scales[NL];
__device__ float g_red_xy[NXY];
__device__ float g_red_xz[NPL];
__device__ float g_red_yz[NPL];

// ---------------------------------------------------------------------------
// Init scales (double, matches numpy) + fold time-blend and Lagrange basis
// into scalar tables for all three planes.
// ---------------------------------------------------------------------------
__global__ void reduce_all_kernel(const float4* __restrict__ txy,
                                  const float4* __restrict__ txz,
                                  const float4* __restrict__ tyz,
                                  const float* __restrict__ tptr) {
    int g = blockIdx.x * blockDim.x + threadIdx.x;
    if (g < NL) {
        double s = exp2((double)g * (6.0 / 7.0)) * 512.0 - 1.0;
        g_scales[g] = (float)s;
    }

    float t = __ldg(tptr);
    float idxf = t * 7.0f;               // t * (TIME_RES - 1)
    float fi1 = floorf(idxf);
    int i1 = (int)fi1;
    int i2 = (int)ceilf(idxf);
    float w2 = idxf - fi1;
    float w1 = 1.0f - w2;

    float tn[4] = {0.0f, 1.0f / 3.0f, 2.0f / 3.0f, 1.0f};
    float coef[4];
#pragma unroll
    for (int ii = 0; ii < 4; ii++) {
        float c = 1.0f;
#pragma unroll
        for (int m = 0; m < 4; m++)
            if (m != ii) c = c * (t - tn[m]) / (tn[ii] - tn[m]);
        coef[ii] = c;
    }

    const float4* tab;
    float* dst;
    int e, total;
    if (g < (int)NXY)                  { tab = txy; dst = g_red_xy; e = g;             total = NXY; }
    else if (g < (int)(NXY + NPL))     { tab = txz; dst = g_red_xz; e = g - NXY;       total = NPL; }
    else if (g < (int)(NXY + 2 * NPL)) { tab = tyz; dst = g_red_yz; e = g - NXY - NPL; total = NPL; }
    else return;

    float4 v1 = __ldg(tab + (size_t)i1 * total + e);
    float4 v2 = __ldg(tab + (size_t)i2 * total + e);
    dst[e] = coef[0] * (w1 * v1.x + w2 * v2.x)
           + coef[1] * (w1 * v1.y + w2 * v2.y)
           + coef[2] * (w1 * v1.z + w2 * v2.z)
           + coef[3] * (w1 * v1.w + w2 * v2.w);
}

// ---------------------------------------------------------------------------
// Static 3D hash-grid: one thread per (point, level). 8 independent gathers
// per thread, fully coalesced float4 stores (level is the fast thread index).
// ---------------------------------------------------------------------------
__global__ void __launch_bounds__(256)
static_kernel(const float* __restrict__ x,
              const float4* __restrict__ tstat,
              float4* __restrict__ out_s,   // [N*8] float4, level-major per point
              int total /* N*8 */) {
    int g = blockIdx.x * blockDim.x + threadIdx.x;
    if (g >= total) return;
    int p = g >> 3;
    int l = g & 7;

    float x0 = __ldg(x + 3 * (size_t)p + 0);
    float x1 = __ldg(x + 3 * (size_t)p + 1);
    float x2 = __ldg(x + 3 * (size_t)p + 2);

    float scl = g_scales[l];
    float px = __fadd_rn(__fmul_rn(x0, scl), 0.5f);
    float py = __fadd_rn(__fmul_rn(x1, scl), 0.5f);
    float pz = __fadd_rn(__fmul_rn(x2, scl), 0.5f);
    float bx = floorf(px), by = floorf(py), bz = floorf(pz);
    float fx = px - bx, fy = py - by, fz = pz - bz;
    uint32_t ux = (uint32_t)bx, uy = (uint32_t)by, uz = (uint32_t)bz;
    uint32_t hx0 = ux,      hx1 = ux + 1u;
    uint32_t hy0 = uy * P1, hy1 = hy0 + P1;
    uint32_t hz0 = uz * P2, hz1 = hz0 + P2;
    float gx = 1.0f - fx, gy = 1.0f - fy, gz = 1.0f - fz;
    const float4* tl = tstat + (size_t)l * T_STATIC;

    // issue all 8 gathers before consuming (max MLP)
    float4 v[8];
#pragma unroll
    for (int c = 0; c < 8; c++) {
        uint32_t h = ((c & 1) ? hx1 : hx0)
                   ^ ((c & 2) ? hy1 : hy0)
                   ^ ((c & 4) ? hz1 : hz0);
        v[c] = __ldg(tl + (h & (T_STATIC - 1u)));
    }

    float a0 = 0.f, a1 = 0.f, a2 = 0.f, a3 = 0.f;
#pragma unroll
    for (int c = 0; c < 8; c++) {
        float w = (((c & 1) ? fx : gx) * ((c & 2) ? fy : gy))
                * ((c & 4) ? fz : gz);
        a0 += w * v[c].x; a1 += w * v[c].y; a2 += w * v[c].z; a3 += w * v[c].w;
    }
    out_s[g] = make_float4(a0, a1, a2, a3);
}

// ---------------------------------------------------------------------------
// Dynamic planes: one thread per (point, plane). 8 levels x ~3 loads each
// (even-ua corners pair into one float2). Stores fully coalesced: thread
// (p, plane) writes 32B at out_d + p*96 + plane*32.
// ---------------------------------------------------------------------------
__global__ void __launch_bounds__(256)
dyn_kernel(const float* __restrict__ x,
           float4* __restrict__ out_d,   // [N*6] float4
           int total /* N*3 */) {
    int g = blockIdx.x * blockDim.x + threadIdx.x;
    if (g >= total) return;
    unsigned p = (unsigned)g / 3u;
    unsigned plane = (unsigned)g - 3u * p;

    float x0 = __ldg(x + 3 * (size_t)p + 0);
    float x1 = __ldg(x + 3 * (size_t)p + 1);
    float x2 = __ldg(x + 3 * (size_t)p + 2);

    float a = (plane == 2u) ? x1 : x0;
    float b = (plane == 0u) ? x1 : x2;
    const float* red = (plane == 0u) ? g_red_xy
                     : (plane == 1u) ? g_red_xz : g_red_yz;
    uint32_t mask = (plane == 0u) ? (T_XY - 1u) : (T_PL - 1u);
    uint32_t tsize = mask + 1u;

    float d8[NL];
#pragma unroll
    for (int l = 0; l < NL; l++) {
        float s = g_scales[l];
        float pa = __fadd_rn(__fmul_rn(a, s), 0.5f);
        float pb = __fadd_rn(__fmul_rn(b, s), 0.5f);
        float ba = floorf(pa), bb = floorf(pb);
        float fa = pa - ba, fb = pb - bb;
        uint32_t ua = (uint32_t)ba, ub = (uint32_t)bb;
        uint32_t hb0 = ub * P1, hb1 = hb0 + P1;
        uint32_t e00 = (ua ^ hb0) & mask;
        uint32_t e01 = (ua ^ hb1) & mask;
        const float* r = red + (size_t)l * tsize;

        float v00, v10, v01, v11;
        if ((ua & 1u) == 0u) {
            // e10 == e00^1, e11 == e01^1 (no carry out of bit 0)
            float2 q0 = __ldg((const float2*)(r + (e00 & ~1u)));
            float2 q1 = __ldg((const float2*)(r + (e01 & ~1u)));
            if (e00 & 1u) { v00 = q0.y; v10 = q0.x; } else { v00 = q0.x; v10 = q0.y; }
            if (e01 & 1u) { v01 = q1.y; v11 = q1.x; } else { v01 = q1.x; v11 = q1.y; }
        } else {
            uint32_t e10 = ((ua + 1u) ^ hb0) & mask;
            uint32_t e11 = ((ua + 1u) ^ hb1) & mask;
            v00 = __ldg(r + e00); v10 = __ldg(r + e10);
            v01 = __ldg(r + e01); v11 = __ldg(r + e11);
        }

        float ga = 1.0f - fa, gb = 1.0f - fb;
        float acc = (ga * gb) * v00;
        acc += (fa * gb) * v10;
        acc += (ga * fb) * v01;
        acc += (fa * fb) * v11;
        d8[l] = acc;
    }

    float4* od = out_d + (size_t)g * 2;
    od[0] = make_float4(d8[0], d8[1], d8[2], d8[3]);
    od[1] = make_float4(d8[4], d8[5], d8[6], d8[7]);
}

// ---------------------------------------------------------------------------
extern "C" void kernel_launch(void* const* d_in, const int* in_sizes, int n_in,
                              void* d_out, int out_size) {
    const float* x     = (const float*)d_in[0];
    const float* tptr  = (const float*)d_in[1];
    const float* tstat = (const float*)d_in[2];
    const float* txy   = (const float*)d_in[3];
    const float* txz   = (const float*)d_in[4];
    const float* tyz   = (const float*)d_in[5];

    int N = in_sizes[0] / 3;
    float* out_s = (float*)d_out;
    float* out_d = (float*)d_out + (size_t)N * 32;

    int total_red = NXY + 2 * NPL;
    reduce_all_kernel<<<(total_red + 255) / 256, 256>>>(
        (const float4*)txy, (const float4*)txz, (const float4*)tyz, tptr);

    int tot_s = N * 8;
    static_kernel<<<(tot_s + 255) / 256, 256>>>(x, (const float4*)tstat,
                                                (float4*)out_s, tot_s);

    int tot_d = N * 3;
    dyn_kernel<<<(tot_d + 255) / 256, 256>>>(x, (float4*)out_d, tot_d);
}

// round 6
// speedup vs baseline: 1.4457x; 1.0104x over previous
#include <cuda_runtime.h>
#include <cstdint>

#define NL 8
#define T_STATIC 524288u   // 2^19
#define T_XY     32768u    // 2^15
#define T_PL     8192u     // 2^13
#define P1 2654435761u
#define P2 805459861u

#define NXY (NL * T_XY)    // 262144
#define NPL (NL * T_PL)    // 65536

__device__ float g_scales[NL];
__device__ float g_red_xy[NXY];
__device__ float g_red_xz[NPL];
__device__ float g_red_yz[NPL];

// ---------------------------------------------------------------------------
// Init scales (double, matches numpy) + fold time-blend and Lagrange basis
// into scalar tables for all three planes.
// ---------------------------------------------------------------------------
__global__ void reduce_all_kernel(const float4* __restrict__ txy,
                                  const float4* __restrict__ txz,
                                  const float4* __restrict__ tyz,
                                  const float* __restrict__ tptr) {
    int g = blockIdx.x * blockDim.x + threadIdx.x;
    if (g < NL) {
        double s = exp2((double)g * (6.0 / 7.0)) * 512.0 - 1.0;
        g_scales[g] = (float)s;
    }

    float t = __ldg(tptr);
    float idxf = t * 7.0f;               // t * (TIME_RES - 1)
    float fi1 = floorf(idxf);
    int i1 = (int)fi1;
    int i2 = (int)ceilf(idxf);
    float w2 = idxf - fi1;
    float w1 = 1.0f - w2;

    float tn[4] = {0.0f, 1.0f / 3.0f, 2.0f / 3.0f, 1.0f};
    float coef[4];
#pragma unroll
    for (int ii = 0; ii < 4; ii++) {
        float c = 1.0f;
#pragma unroll
        for (int m = 0; m < 4; m++)
            if (m != ii) c = c * (t - tn[m]) / (tn[ii] - tn[m]);
        coef[ii] = c;
    }

    const float4* tab;
    float* dst;
    int e, total;
    if (g < (int)NXY)                  { tab = txy; dst = g_red_xy; e = g;             total = NXY; }
    else if (g < (int)(NXY + NPL))     { tab = txz; dst = g_red_xz; e = g - NXY;       total = NPL; }
    else if (g < (int)(NXY + 2 * NPL)) { tab = tyz; dst = g_red_yz; e = g - NXY - NPL; total = NPL; }
    else return;

    float4 v1 = __ldg(tab + (size_t)i1 * total + e);
    float4 v2 = __ldg(tab + (size_t)i2 * total + e);
    dst[e] = coef[0] * (w1 * v1.x + w2 * v2.x)
           + coef[1] * (w1 * v1.y + w2 * v2.y)
           + coef[2] * (w1 * v1.z + w2 * v2.z)
           + coef[3] * (w1 * v1.w + w2 * v2.w);
}

// ---------------------------------------------------------------------------
// Static 3D hash-grid, corner-per-lane layout: warp = 4 points x 8 corners,
// looping over 8 levels. x-paired corners (lanes 2k/2k+1) hit the SAME 128B
// line whenever ux is even (hash prime for x is 1 => indices e, e^1), so L1
// merges them into one wavefront: expected 6 lines per point-level vs 8.
// Cross-lane sum via 3 butterfly shuffles; lane c keeps level c's float4 so
// final stores are 512B contiguous per warp.
// ---------------------------------------------------------------------------
__global__ void __launch_bounds__(256)
static_kernel(const float* __restrict__ x,
              const float4* __restrict__ tstat,
              float4* __restrict__ out_s,   // [N*8] float4, level-major per point
              int N) {
    int warp_g = (blockIdx.x * 256 + threadIdx.x) >> 5;
    int lane = threadIdx.x & 31;
    int pg = warp_g * 4 + (lane >> 3);        // point id this lane serves
    unsigned c = (unsigned)lane & 7u;         // corner id
    int p = (pg < N) ? pg : (N - 1);          // clamp for safe loads

    float x0 = __ldg(x + 3 * (size_t)p + 0);
    float x1 = __ldg(x + 3 * (size_t)p + 1);
    float x2 = __ldg(x + 3 * (size_t)p + 2);

    uint32_t cx = c & 1u, cy = (c >> 1) & 1u, cz = (c >> 2) & 1u;

    float o0 = 0.f, o1 = 0.f, o2 = 0.f, o3 = 0.f;

#pragma unroll
    for (int l = 0; l < NL; l++) {
        float scl = g_scales[l];
        float px = __fadd_rn(__fmul_rn(x0, scl), 0.5f);
        float py = __fadd_rn(__fmul_rn(x1, scl), 0.5f);
        float pz = __fadd_rn(__fmul_rn(x2, scl), 0.5f);
        float bx = floorf(px), by = floorf(py), bz = floorf(pz);
        float fx = px - bx, fy = py - by, fz = pz - bz;
        uint32_t ux = (uint32_t)bx, uy = (uint32_t)by, uz = (uint32_t)bz;

        uint32_t h = (ux + cx) ^ (uy * P1 + (cy ? P1 : 0u))
                               ^ (uz * P2 + (cz ? P2 : 0u));
        float w = (cx ? fx : 1.0f - fx) * (cy ? fy : 1.0f - fy)
                * (cz ? fz : 1.0f - fz);

        float4 v = __ldg(tstat + (size_t)l * T_STATIC + (h & (T_STATIC - 1u)));

        float b0 = w * v.x, b1 = w * v.y, b2 = w * v.z, b3 = w * v.w;
#pragma unroll
        for (int off = 1; off < 8; off <<= 1) {
            b0 += __shfl_xor_sync(0xffffffffu, b0, off);
            b1 += __shfl_xor_sync(0xffffffffu, b1, off);
            b2 += __shfl_xor_sync(0xffffffffu, b2, off);
            b3 += __shfl_xor_sync(0xffffffffu, b3, off);
        }
        if (c == (unsigned)l) { o0 = b0; o1 = b1; o2 = b2; o3 = b3; }
    }

    if (pg < N)
        out_s[(size_t)pg * 8 + c] = make_float4(o0, o1, o2, o3);
}

// ---------------------------------------------------------------------------
// Dynamic planes: one thread per (point, plane). 8 levels x ~3 loads each
// (even-ua corners pair into one float2). Coalesced 32B stores per thread.
// ---------------------------------------------------------------------------
__global__ void __launch_bounds__(256)
dyn_kernel(const float* __restrict__ x,
           float4* __restrict__ out_d,   // [N*6] float4
           int total /* N*3 */) {
    int g = blockIdx.x * blockDim.x + threadIdx.x;
    if (g >= total) return;
    unsigned p = (unsigned)g / 3u;
    unsigned plane = (unsigned)g - 3u * p;

    float x0 = __ldg(x + 3 * (size_t)p + 0);
    float x1 = __ldg(x + 3 * (size_t)p + 1);
    float x2 = __ldg(x + 3 * (size_t)p + 2);

    float a = (plane == 2u) ? x1 : x0;
    float b = (plane == 0u) ? x1 : x2;
    const float* red = (plane == 0u) ? g_red_xy
                     : (plane == 1u) ? g_red_xz : g_red_yz;
    uint32_t mask = (plane == 0u) ? (T_XY - 1u) : (T_PL - 1u);
    uint32_t tsize = mask + 1u;

    float d8[NL];
#pragma unroll
    for (int l = 0; l < NL; l++) {
        float s = g_scales[l];
        float pa = __fadd_rn(__fmul_rn(a, s), 0.5f);
        float pb = __fadd_rn(__fmul_rn(b, s), 0.5f);
        float ba = floorf(pa), bb = floorf(pb);
        float fa = pa - ba, fb = pb - bb;
        uint32_t ua = (uint32_t)ba, ub = (uint32_t)bb;
        uint32_t hb0 = ub * P1, hb1 = hb0 + P1;
        uint32_t e00 = (ua ^ hb0) & mask;
        uint32_t e01 = (ua ^ hb1) & mask;
        const float* r = red + (size_t)l * tsize;

        float v00, v10, v01, v11;
        if ((ua & 1u) == 0u) {
            // e10 == e00^1, e11 == e01^1 (no carry out of bit 0)
            float2 q0 = __ldg((const float2*)(r + (e00 & ~1u)));
            float2 q1 = __ldg((const float2*)(r + (e01 & ~1u)));
            if (e00 & 1u) { v00 = q0.y; v10 = q0.x; } else { v00 = q0.x; v10 = q0.y; }
            if (e01 & 1u) { v01 = q1.y; v11 = q1.x; } else { v01 = q1.x; v11 = q1.y; }
        } else {
            uint32_t e10 = ((ua + 1u) ^ hb0) & mask;
            uint32_t e11 = ((ua + 1u) ^ hb1) & mask;
            v00 = __ldg(r + e00); v10 = __ldg(r + e10);
            v01 = __ldg(r + e01); v11 = __ldg(r + e11);
        }

        float ga = 1.0f - fa, gb = 1.0f - fb;
        float acc = (ga * gb) * v00;
        acc += (fa * gb) * v10;
        acc += (ga * fb) * v01;
        acc += (fa * fb) * v11;
        d8[l] = acc;
    }

    float4* od = out_d + (size_t)g * 2;
    od[0] = make_float4(d8[0], d8[1], d8[2], d8[3]);
    od[1] = make_float4(d8[4], d8[5], d8[6], d8[7]);
}

// ---------------------------------------------------------------------------
extern "C" void kernel_launch(void* const* d_in, const int* in_sizes, int n_in,
                              void* d_out, int out_size) {
    const float* x     = (const float*)d_in[0];
    const float* tptr  = (const float*)d_in[1];
    const float* tstat = (const float*)d_in[2];
    const float* txy   = (const float*)d_in[3];
    const float* txz   = (const float*)d_in[4];
    const float* tyz   = (const float*)d_in[5];

    int N = in_sizes[0] / 3;
    float* out_s = (float*)d_out;
    float* out_d = (float*)d_out + (size_t)N * 32;

    int total_red = NXY + 2 * NPL;
    reduce_all_kernel<<<(total_red + 255) / 256, 256>>>(
        (const float4*)txy, (const float4*)txz, (const float4*)tyz, tptr);

    int tot_d = N * 3;
    dyn_kernel<<<(tot_d + 255) / 256, 256>>>(x, (float4*)out_d, tot_d);

    // static last so ncu's -s 5 lands on it (it has no dependency on reduce)
    int nwarps = (N + 3) / 4;
    int nblocks = (nwarps + 7) / 8;           // 8 warps per 256-thread block
    static_kernel<<<nblocks, 256>>>(x, (const float4*)tstat, (float4*)out_s, N);
}

// round 7
// speedup vs baseline: 1.4459x; 1.0002x over previous
#include <cuda_runtime.h>
#include <cstdint>

#define NL 8
#define T_STATIC 524288u   // 2^19
#define T_XY     32768u    // 2^15
#define T_PL     8192u     // 2^13
#define P1 2654435761u
#define P2 805459861u

#define NXY (NL * T_XY)    // 262144
#define NPL (NL * T_PL)    // 65536

__device__ float g_scales[NL];
__device__ float g_red_xy[NXY];
__device__ float g_red_xz[NPL];
__device__ float g_red_yz[NPL];

// ---------------------------------------------------------------------------
// Init scales (double, matches numpy) + fold time-blend and Lagrange basis
// into scalar tables for all three planes.
// ---------------------------------------------------------------------------
__global__ void reduce_all_kernel(const float4* __restrict__ txy,
                                  const float4* __restrict__ txz,
                                  const float4* __restrict__ tyz,
                                  const float* __restrict__ tptr) {
    int g = blockIdx.x * blockDim.x + threadIdx.x;
    if (g < NL) {
        double s = exp2((double)g * (6.0 / 7.0)) * 512.0 - 1.0;
        g_scales[g] = (float)s;
    }

    float t = __ldg(tptr);
    float idxf = t * 7.0f;               // t * (TIME_RES - 1)
    float fi1 = floorf(idxf);
    int i1 = (int)fi1;
    int i2 = (int)ceilf(idxf);
    float w2 = idxf - fi1;
    float w1 = 1.0f - w2;

    float tn[4] = {0.0f, 1.0f / 3.0f, 2.0f / 3.0f, 1.0f};
    float coef[4];
#pragma unroll
    for (int ii = 0; ii < 4; ii++) {
        float c = 1.0f;
#pragma unroll
        for (int m = 0; m < 4; m++)
            if (m != ii) c = c * (t - tn[m]) / (tn[ii] - tn[m]);
        coef[ii] = c;
    }

    const float4* tab;
    float* dst;
    int e, total;
    if (g < (int)NXY)                  { tab = txy; dst = g_red_xy; e = g;             total = NXY; }
    else if (g < (int)(NXY + NPL))     { tab = txz; dst = g_red_xz; e = g - NXY;       total = NPL; }
    else if (g < (int)(NXY + 2 * NPL)) { tab = tyz; dst = g_red_yz; e = g - NXY - NPL; total = NPL; }
    else return;

    float4 v1 = __ldg(tab + (size_t)i1 * total + e);
    float4 v2 = __ldg(tab + (size_t)i2 * total + e);
    dst[e] = coef[0] * (w1 * v1.x + w2 * v2.x)
           + coef[1] * (w1 * v1.y + w2 * v2.y)
           + coef[2] * (w1 * v1.z + w2 * v2.z)
           + coef[3] * (w1 * v1.w + w2 * v2.w);
}

// ---------------------------------------------------------------------------
// Static 3D hash-grid, corner-per-lane layout: warp = 4 points x 8 corners,
// looping over 8 levels. x-paired corners (lanes 2k/2k+1) hit the SAME 128B
// line whenever ux is even (hash prime for x is 1 => indices e, e^1), so L1
// merges them into one wavefront: expected 6 lines per point-level vs 8.
// Cross-lane sum via 3 butterfly shuffles; lane c keeps level c's float4 so
// final stores are 512B contiguous per warp.
// ---------------------------------------------------------------------------
__global__ void __launch_bounds__(256)
static_kernel(const float* __restrict__ x,
              const float4* __restrict__ tstat,
              float4* __restrict__ out_s,   // [N*8] float4, level-major per point
              int N) {
    int warp_g = (blockIdx.x * 256 + threadIdx.x) >> 5;
    int lane = threadIdx.x & 31;
    int pg = warp_g * 4 + (lane >> 3);        // point id this lane serves
    unsigned c = (unsigned)lane & 7u;         // corner id
    int p = (pg < N) ? pg : (N - 1);          // clamp for safe loads

    float x0 = __ldg(x + 3 * (size_t)p + 0);
    float x1 = __ldg(x + 3 * (size_t)p + 1);
    float x2 = __ldg(x + 3 * (size_t)p + 2);

    uint32_t cx = c & 1u, cy = (c >> 1) & 1u, cz = (c >> 2) & 1u;

    float o0 = 0.f, o1 = 0.f, o2 = 0.f, o3 = 0.f;

#pragma unroll
    for (int l = 0; l < NL; l++) {
        float scl = g_scales[l];
        float px = __fadd_rn(__fmul_rn(x0, scl), 0.5f);
        float py = __fadd_rn(__fmul_rn(x1, scl), 0.5f);
        float pz = __fadd_rn(__fmul_rn(x2, scl), 0.5f);
        float bx = floorf(px), by = floorf(py), bz = floorf(pz);
        float fx = px - bx, fy = py - by, fz = pz - bz;
        uint32_t ux = (uint32_t)bx, uy = (uint32_t)by, uz = (uint32_t)bz;

        uint32_t h = (ux + cx) ^ (uy * P1 + (cy ? P1 : 0u))
                               ^ (uz * P2 + (cz ? P2 : 0u));
        float w = (cx ? fx : 1.0f - fx) * (cy ? fy : 1.0f - fy)
                * (cz ? fz : 1.0f - fz);

        float4 v = __ldg(tstat + (size_t)l * T_STATIC + (h & (T_STATIC - 1u)));

        float b0 = w * v.x, b1 = w * v.y, b2 = w * v.z, b3 = w * v.w;
#pragma unroll
        for (int off = 1; off < 8; off <<= 1) {
            b0 += __shfl_xor_sync(0xffffffffu, b0, off);
            b1 += __shfl_xor_sync(0xffffffffu, b1, off);
            b2 += __shfl_xor_sync(0xffffffffu, b2, off);
            b3 += __shfl_xor_sync(0xffffffffu, b3, off);
        }
        if (c == (unsigned)l) { o0 = b0; o1 = b1; o2 = b2; o3 = b3; }
    }

    if (pg < N)
        out_s[(size_t)pg * 8 + c] = make_float4(o0, o1, o2, o3);
}

// ---------------------------------------------------------------------------
// Dynamic planes: one thread per (point, plane). 8 levels x ~3 loads each
// (even-ua corners pair into one float2). Coalesced 32B stores per thread.
// ---------------------------------------------------------------------------
__global__ void __launch_bounds__(256)
dyn_kernel(const float* __restrict__ x,
           float4* __restrict__ out_d,   // [N*6] float4
           int total /* N*3 */) {
    int g = blockIdx.x * blockDim.x + threadIdx.x;
    if (g >= total) return;
    unsigned p = (unsigned)g / 3u;
    unsigned plane = (unsigned)g - 3u * p;

    float x0 = __ldg(x + 3 * (size_t)p + 0);
    float x1 = __ldg(x + 3 * (size_t)p + 1);
    float x2 = __ldg(x + 3 * (size_t)p + 2);

    float a = (plane == 2u) ? x1 : x0;
    float b = (plane == 0u) ? x1 : x2;
    const float* red = (plane == 0u) ? g_red_xy
                     : (plane == 1u) ? g_red_xz : g_red_yz;
    uint32_t mask = (plane == 0u) ? (T_XY - 1u) : (T_PL - 1u);
    uint32_t tsize = mask + 1u;

    float d8[NL];
#pragma unroll
    for (int l = 0; l < NL; l++) {
        float s = g_scales[l];
        float pa = __fadd_rn(__fmul_rn(a, s), 0.5f);
        float pb = __fadd_rn(__fmul_rn(b, s), 0.5f);
        float ba = floorf(pa), bb = floorf(pb);
        float fa = pa - ba, fb = pb - bb;
        uint32_t ua = (uint32_t)ba, ub = (uint32_t)bb;
        uint32_t hb0 = ub * P1, hb1 = hb0 + P1;
        uint32_t e00 = (ua ^ hb0) & mask;
        uint32_t e01 = (ua ^ hb1) & mask;
        const float* r = red + (size_t)l * tsize;

        float v00, v10, v01, v11;
        if ((ua & 1u) == 0u) {
            // e10 == e00^1, e11 == e01^1 (no carry out of bit 0)
            float2 q0 = __ldg((const float2*)(r + (e00 & ~1u)));
            float2 q1 = __ldg((const float2*)(r + (e01 & ~1u)));
            if (e00 & 1u) { v00 = q0.y; v10 = q0.x; } else { v00 = q0.x; v10 = q0.y; }
            if (e01 & 1u) { v01 = q1.y; v11 = q1.x; } else { v01 = q1.x; v11 = q1.y; }
        } else {
            uint32_t e10 = ((ua + 1u) ^ hb0) & mask;
            uint32_t e11 = ((ua + 1u) ^ hb1) & mask;
            v00 = __ldg(r + e00); v10 = __ldg(r + e10);
            v01 = __ldg(r + e01); v11 = __ldg(r + e11);
        }

        float ga = 1.0f - fa, gb = 1.0f - fb;
        float acc = (ga * gb) * v00;
        acc += (fa * gb) * v10;
        acc += (ga * fb) * v01;
        acc += (fa * fb) * v11;
        d8[l] = acc;
    }

    float4* od = out_d + (size_t)g * 2;
    od[0] = make_float4(d8[0], d8[1], d8[2], d8[3]);
    od[1] = make_float4(d8[4], d8[5], d8[6], d8[7]);
}

// ---------------------------------------------------------------------------
extern "C" void kernel_launch(void* const* d_in, const int* in_sizes, int n_in,
                              void* d_out, int out_size) {
    const float* x     = (const float*)d_in[0];
    const float* tptr  = (const float*)d_in[1];
    const float* tstat = (const float*)d_in[2];
    const float* txy   = (const float*)d_in[3];
    const float* txz   = (const float*)d_in[4];
    const float* tyz   = (const float*)d_in[5];

    int N = in_sizes[0] / 3;
    float* out_s = (float*)d_out;
    float* out_d = (float*)d_out + (size_t)N * 32;

    int total_red = NXY + 2 * NPL;
    reduce_all_kernel<<<(total_red + 255) / 256, 256>>>(
        (const float4*)txy, (const float4*)txz, (const float4*)tyz, tptr);

    int tot_d = N * 3;
    dyn_kernel<<<(tot_d + 255) / 256, 256>>>(x, (float4*)out_d, tot_d);

    // static last so ncu's -s 5 lands on it (it has no dependency on reduce)
    int nwarps = (N + 3) / 4;
    int nblocks = (nwarps + 7) / 8;           // 8 warps per 256-thread block
    static_kernel<<<nblocks, 256>>>(x, (const float4*)tstat, (float4*)out_s, N);
}

// round 8
// speedup vs baseline: 1.4476x; 1.0012x over previous
#include <cuda_runtime.h>
#include <cstdint>

#define NL 8
#define T_STATIC 524288u   // 2^19
#define T_XY     32768u    // 2^15
#define T_PL     8192u     // 2^13
#define P1 2654435761u
#define P2 805459861u

#define NXY (NL * T_XY)    // 262144
#define NPL (NL * T_PL)    // 65536

__device__ float g_scales[NL];
__device__ float g_red_xy[NXY];
__device__ float g_red_xz[NPL];
__device__ float g_red_yz[NPL];

// ---------------------------------------------------------------------------
// Init scales (double, matches numpy) + fold time-blend and Lagrange basis
// into scalar tables for all three planes.
// ---------------------------------------------------------------------------
__global__ void reduce_all_kernel(const float4* __restrict__ txy,
                                  const float4* __restrict__ txz,
                                  const float4* __restrict__ tyz,
                                  const float* __restrict__ tptr) {
    int g = blockIdx.x * blockDim.x + threadIdx.x;
    if (g < NL) {
        double s = exp2((double)g * (6.0 / 7.0)) * 512.0 - 1.0;
        g_scales[g] = (float)s;
    }

    float t = __ldg(tptr);
    float idxf = t * 7.0f;               // t * (TIME_RES - 1)
    float fi1 = floorf(idxf);
    int i1 = (int)fi1;
    int i2 = (int)ceilf(idxf);
    float w2 = idxf - fi1;
    float w1 = 1.0f - w2;

    float tn[4] = {0.0f, 1.0f / 3.0f, 2.0f / 3.0f, 1.0f};
    float coef[4];
#pragma unroll
    for (int ii = 0; ii < 4; ii++) {
        float c = 1.0f;
#pragma unroll
        for (int m = 0; m < 4; m++)
            if (m != ii) c = c * (t - tn[m]) / (tn[ii] - tn[m]);
        coef[ii] = c;
    }

    const float4* tab;
    float* dst;
    int e, total;
    if (g < (int)NXY)                  { tab = txy; dst = g_red_xy; e = g;             total = NXY; }
    else if (g < (int)(NXY + NPL))     { tab = txz; dst = g_red_xz; e = g - NXY;       total = NPL; }
    else if (g < (int)(NXY + 2 * NPL)) { tab = tyz; dst = g_red_yz; e = g - NXY - NPL; total = NPL; }
    else return;

    float4 v1 = __ldg(tab + (size_t)i1 * total + e);
    float4 v2 = __ldg(tab + (size_t)i2 * total + e);
    dst[e] = coef[0] * (w1 * v1.x + w2 * v2.x)
           + coef[1] * (w1 * v1.y + w2 * v2.y)
           + coef[2] * (w1 * v1.z + w2 * v2.z)
           + coef[3] * (w1 * v1.w + w2 * v2.w);
}

// ---------------------------------------------------------------------------
// Static 3D hash-grid, corner-per-lane layout: warp = 4 points x 8 corners,
// looping over 8 levels. x-paired corners (lanes 2k/2k+1) hit the SAME 128B
// line whenever ux is even (hash prime for x is 1 => indices e, e^1), so L1
// merges them into one wavefront: expected 6 lines per point-level vs 8.
// Cross-lane sum via 3 butterfly shuffles; lane c keeps level c's float4 so
// final stores are 512B contiguous per warp.
// ---------------------------------------------------------------------------
__global__ void __launch_bounds__(256)
static_kernel(const float* __restrict__ x,
              const float4* __restrict__ tstat,
              float4* __restrict__ out_s,   // [N*8] float4, level-major per point
              int N) {
    int warp_g = (blockIdx.x * 256 + threadIdx.x) >> 5;
    int lane = threadIdx.x & 31;
    int pg = warp_g * 4 + (lane >> 3);        // point id this lane serves
    unsigned c = (unsigned)lane & 7u;         // corner id
    int p = (pg < N) ? pg : (N - 1);          // clamp for safe loads

    float x0 = __ldg(x + 3 * (size_t)p + 0);
    float x1 = __ldg(x + 3 * (size_t)p + 1);
    float x2 = __ldg(x + 3 * (size_t)p + 2);

    uint32_t cx = c & 1u, cy = (c >> 1) & 1u, cz = (c >> 2) & 1u;

    float o0 = 0.f, o1 = 0.f, o2 = 0.f, o3 = 0.f;

#pragma unroll
    for (int l = 0; l < NL; l++) {
        float scl = g_scales[l];
        float px = __fadd_rn(__fmul_rn(x0, scl), 0.5f);
        float py = __fadd_rn(__fmul_rn(x1, scl), 0.5f);
        float pz = __fadd_rn(__fmul_rn(x2, scl), 0.5f);
        float bx = floorf(px), by = floorf(py), bz = floorf(pz);
        float fx = px - bx, fy = py - by, fz = pz - bz;
        uint32_t ux = (uint32_t)bx, uy = (uint32_t)by, uz = (uint32_t)bz;

        uint32_t h = (ux + cx) ^ (uy * P1 + (cy ? P1 : 0u))
                               ^ (uz * P2 + (cz ? P2 : 0u));
        float w = (cx ? fx : 1.0f - fx) * (cy ? fy : 1.0f - fy)
                * (cz ? fz : 1.0f - fz);

        float4 v = __ldg(tstat + (size_t)l * T_STATIC + (h & (T_STATIC - 1u)));

        float b0 = w * v.x, b1 = w * v.y, b2 = w * v.z, b3 = w * v.w;
#pragma unroll
        for (int off = 1; off < 8; off <<= 1) {
            b0 += __shfl_xor_sync(0xffffffffu, b0, off);
            b1 += __shfl_xor_sync(0xffffffffu, b1, off);
            b2 += __shfl_xor_sync(0xffffffffu, b2, off);
            b3 += __shfl_xor_sync(0xffffffffu, b3, off);
        }
        if (c == (unsigned)l) { o0 = b0; o1 = b1; o2 = b2; o3 = b3; }
    }

    if (pg < N)
        out_s[(size_t)pg * 8 + c] = make_float4(o0, o1, o2, o3);
}

// ---------------------------------------------------------------------------
// Dynamic planes: one thread per (point, plane). 8 levels x ~3 loads each
// (even-ua corners pair into one float2). Coalesced 32B stores per thread.
// ---------------------------------------------------------------------------
__global__ void __launch_bounds__(256)
dyn_kernel(const float* __restrict__ x,
           float4* __restrict__ out_d,   // [N*6] float4
           int total /* N*3 */) {
    int g = blockIdx.x * blockDim.x + threadIdx.x;
    if (g >= total) return;
    unsigned p = (unsigned)g / 3u;
    unsigned plane = (unsigned)g - 3u * p;

    float x0 = __ldg(x + 3 * (size_t)p + 0);
    float x1 = __ldg(x + 3 * (size_t)p + 1);
    float x2 = __ldg(x + 3 * (size_t)p + 2);

    float a = (plane == 2u) ? x1 : x0;
    float b = (plane == 0u) ? x1 : x2;
    const float* red = (plane == 0u) ? g_red_xy
                     : (plane == 1u) ? g_red_xz : g_red_yz;
    uint32_t mask = (plane == 0u) ? (T_XY - 1u) : (T_PL - 1u);
    uint32_t tsize = mask + 1u;

    float d8[NL];
#pragma unroll
    for (int l = 0; l < NL; l++) {
        float s = g_scales[l];
        float pa = __fadd_rn(__fmul_rn(a, s), 0.5f);
        float pb = __fadd_rn(__fmul_rn(b, s), 0.5f);
        float ba = floorf(pa), bb = floorf(pb);
        float fa = pa - ba, fb = pb - bb;
        uint32_t ua = (uint32_t)ba, ub = (uint32_t)bb;
        uint32_t hb0 = ub * P1, hb1 = hb0 + P1;
        uint32_t e00 = (ua ^ hb0) & mask;
        uint32_t e01 = (ua ^ hb1) & mask;
        const float* r = red + (size_t)l * tsize;

        float v00, v10, v01, v11;
        if ((ua & 1u) == 0u) {
            // e10 == e00^1, e11 == e01^1 (no carry out of bit 0)
            float2 q0 = __ldg((const float2*)(r + (e00 & ~1u)));
            float2 q1 = __ldg((const float2*)(r + (e01 & ~1u)));
            if (e00 & 1u) { v00 = q0.y; v10 = q0.x; } else { v00 = q0.x; v10 = q0.y; }
            if (e01 & 1u) { v01 = q1.y; v11 = q1.x; } else { v01 = q1.x; v11 = q1.y; }
        } else {
            uint32_t e10 = ((ua + 1u) ^ hb0) & mask;
            uint32_t e11 = ((ua + 1u) ^ hb1) & mask;
            v00 = __ldg(r + e00); v10 = __ldg(r + e10);
            v01 = __ldg(r + e01); v11 = __ldg(r + e11);
        }

        float ga = 1.0f - fa, gb = 1.0f - fb;
        float acc = (ga * gb) * v00;
        acc += (fa * gb) * v10;
        acc += (ga * fb) * v01;
        acc += (fa * fb) * v11;
        d8[l] = acc;
    }

    float4* od = out_d + (size_t)g * 2;
    od[0] = make_float4(d8[0], d8[1], d8[2], d8[3]);
    od[1] = make_float4(d8[4], d8[5], d8[6], d8[7]);
}

// ---------------------------------------------------------------------------
extern "C" void kernel_launch(void* const* d_in, const int* in_sizes, int n_in,
                              void* d_out, int out_size) {
    const float* x     = (const float*)d_in[0];
    const float* tptr  = (const float*)d_in[1];
    const float* tstat = (const float*)d_in[2];
    const float* txy   = (const float*)d_in[3];
    const float* txz   = (const float*)d_in[4];
    const float* tyz   = (const float*)d_in[5];

    int N = in_sizes[0] / 3;
    float* out_s = (float*)d_out;
    float* out_d = (float*)d_out + (size_t)N * 32;

    int total_red = NXY + 2 * NPL;
    reduce_all_kernel<<<(total_red + 255) / 256, 256>>>(
        (const float4*)txy, (const float4*)txz, (const float4*)tyz, tptr);

    int tot_d = N * 3;
    dyn_kernel<<<(tot_d + 255) / 256, 256>>>(x, (float4*)out_d, tot_d);

    // static last so ncu's -s 5 lands on it (it has no dependency on reduce)
    int nwarps = (N + 3) / 4;
    int nblocks = (nwarps + 7) / 8;           // 8 warps per 256-thread block
    static_kernel<<<nblocks, 256>>>(x, (const float4*)tstat, (float4*)out_s, N);
}